// round 3
// baseline (speedup 1.0000x reference)
#include <cuda_runtime.h>

// Problem constants
#define Bn   4
#define Hq   512
#define Wq   512
#define Cn   128
#define Hon  502
#define Won  502
#define OFFS 2
// Tiling
#define TH   8      // output rows per block
#define TW   64     // output cols per block
#define WT   4      // output cols per thread
#define CCK  8      // channel chunk
#define QW   72     // TW + 8 (halo)
#define QR   10     // q rows per dy-group: TH + 2
#define PPAD 68     // padded p width
#define QPAD 76     // padded q width
#define NTX  16
#define NTY  8
#define NTHR 128

// Packed fp32x2 helpers (sm_103a)
#define FMA2(d, a, b) asm("fma.rn.f32x2 %0, %1, %2, %0;" : "+l"(d) : "l"(a), "l"(b))
#define PACK2(r, lo, hi) asm("mov.b64 %0, {%1, %2};" : "=l"(r) : "f"(lo), "f"(hi))
#define UNPACK2(lo, hi, r) asm("mov.b64 {%0, %1}, %2;" : "=f"(lo), "=f"(hi) : "l"(r))

__global__ __launch_bounds__(NTHR, 3)
void corr9x9_kernel(const float* __restrict__ pg,
                    const float* __restrict__ qg,
                    float* __restrict__ outg)
{
    __shared__ __align__(16) float p_s[TH][CCK][PPAD];
    __shared__ __align__(16) float q_s[QR][CCK][QPAD];

    const int tx  = threadIdx.x;
    const int ty  = threadIdx.y;
    const int tid = ty * NTX + tx;

    const int wo0 = blockIdx.x * TW;
    const int ho0 = blockIdx.y * TH;
    const int b   = blockIdx.z;

    const float* pb = pg + (size_t)b * Hon * Won * Cn;
    const float* qb = qg + (size_t)b * Hq  * Wq  * Cn;

    const int ho = ho0 + ty;

    // ---- precompute staging addresses (constant across chunks/groups) ----
    // p staging: 8 iterations
    const float* p_src[8];
    int p_c4[8], p_w[8], p_row[8];
    #pragma unroll
    for (int it = 0; it < 8; ++it) {
        int flat = tid + it * NTHR;
        int c4   = flat & 1;
        int w    = (flat >> 1) & (TW - 1);
        int row  = flat >> 7;
        int hr   = ho0 + row; if (hr > Hon - 1) hr = Hon - 1;
        int wr   = wo0 + w;   if (wr > Won - 1) wr = Won - 1;
        p_src[it] = pb + ((size_t)hr * Won + wr) * Cn + c4 * 4;
        p_c4[it] = c4; p_w[it] = w; p_row[it] = row;
    }

    for (int g = 0; g < 3; ++g) {
        // packed accumulators: pixel pairs (0,1) and (2,3); [pair][d][dx]
        unsigned long long acc[2][3][9];
        #pragma unroll
        for (int k = 0; k < 2; ++k)
            #pragma unroll
            for (int d = 0; d < 3; ++d)
                #pragma unroll
                for (int dx = 0; dx < 9; ++dx)
                    acc[k][d][dx] = 0ull;

        const int r0 = ho0 + 3 * g + OFFS;

        for (int cc = 0; cc < Cn; cc += CCK) {
            __syncthreads();

            // ---- stage p: batch all 8 LDGs, then STS ----
            {
                float4 pv[8];
                #pragma unroll
                for (int it = 0; it < 8; ++it)
                    pv[it] = *(const float4*)(p_src[it] + cc);
                #pragma unroll
                for (int it = 0; it < 8; ++it) {
                    p_s[p_row[it]][p_c4[it] * 4 + 0][p_w[it]] = pv[it].x;
                    p_s[p_row[it]][p_c4[it] * 4 + 1][p_w[it]] = pv[it].y;
                    p_s[p_row[it]][p_c4[it] * 4 + 2][p_w[it]] = pv[it].z;
                    p_s[p_row[it]][p_c4[it] * 4 + 3][p_w[it]] = pv[it].w;
                }
            }

            // ---- stage q: two batches of 6 ----
            #pragma unroll
            for (int half = 0; half < 2; ++half) {
                float4 qv[6];
                int qc4[6], qw[6], qrr[6];
                bool ok[6];
                #pragma unroll
                for (int j = 0; j < 6; ++j) {
                    int flat = tid + (half * 6 + j) * NTHR;
                    ok[j] = (flat < QR * QW * 2);
                    int f  = ok[j] ? flat : 0;
                    int c4 = f & 1;
                    int t  = f >> 1;
                    int w  = t % QW;
                    int rr = t / QW;
                    int hr = r0 + rr;        if (hr > Hq - 1) hr = Hq - 1;
                    int wr = wo0 + OFFS + w; if (wr > Wq - 1) wr = Wq - 1;
                    qc4[j] = c4; qw[j] = w; qrr[j] = rr;
                    if (ok[j])
                        qv[j] = *(const float4*)(qb + ((size_t)hr * Wq + wr) * Cn + cc + c4 * 4);
                }
                #pragma unroll
                for (int j = 0; j < 6; ++j) {
                    if (ok[j]) {
                        q_s[qrr[j]][qc4[j] * 4 + 0][qw[j]] = qv[j].x;
                        q_s[qrr[j]][qc4[j] * 4 + 1][qw[j]] = qv[j].y;
                        q_s[qrr[j]][qc4[j] * 4 + 2][qw[j]] = qv[j].z;
                        q_s[qrr[j]][qc4[j] * 4 + 3][qw[j]] = qv[j].w;
                    }
                }
            }

            __syncthreads();

            // ---- packed compute ----
            #pragma unroll
            for (int c = 0; c < CCK; ++c) {
                const float4 pv = *(const float4*)&p_s[ty][c][tx * WT];
                unsigned long long pp2[2];
                PACK2(pp2[0], pv.x, pv.y);
                PACK2(pp2[1], pv.z, pv.w);

                #pragma unroll
                for (int d = 0; d < 3; ++d) {
                    const float4 a0 = *(const float4*)&q_s[ty + d][c][tx * WT];
                    const float4 a1 = *(const float4*)&q_s[ty + d][c][tx * WT + 4];
                    const float4 a2 = *(const float4*)&q_s[ty + d][c][tx * WT + 8];
                    float qv[12] = {a0.x, a0.y, a0.z, a0.w,
                                    a1.x, a1.y, a1.z, a1.w,
                                    a2.x, a2.y, a2.z, a2.w};
                    // pairs pr[j] = (qv[j], qv[j+1]) for j = 0..10
                    unsigned long long pr[11];
                    #pragma unroll
                    for (int j = 0; j < 11; ++j)
                        PACK2(pr[j], qv[j], qv[j + 1]);

                    #pragma unroll
                    for (int dx = 0; dx < 9; ++dx) {
                        FMA2(acc[0][d][dx], pp2[0], pr[dx]);       // pixels 0,1
                        FMA2(acc[1][d][dx], pp2[1], pr[dx + 2]);   // pixels 2,3
                    }
                }
            }
        }

        // ---- write outputs for this dy-group ----
        if (ho < Hon) {
            #pragma unroll
            for (int k = 0; k < 2; ++k) {
                int wo_lo = wo0 + tx * WT + 2 * k;
                int wo_hi = wo_lo + 1;
                #pragma unroll
                for (int d = 0; d < 3; ++d) {
                    size_t base_lo = ((((size_t)b * Hon + ho) * Won + wo_lo) * 9 + (3 * g + d)) * 9;
                    size_t base_hi = ((((size_t)b * Hon + ho) * Won + wo_hi) * 9 + (3 * g + d)) * 9;
                    #pragma unroll
                    for (int dx = 0; dx < 9; ++dx) {
                        float lo, hi;
                        UNPACK2(lo, hi, acc[k][d][dx]);
                        if (wo_lo < Won) __stcs(&outg[base_lo + dx], lo);
                        if (wo_hi < Won) __stcs(&outg[base_hi + dx], hi);
                    }
                }
            }
        }
    }
}

extern "C" void kernel_launch(void* const* d_in, const int* in_sizes, int n_in,
                              void* d_out, int out_size)
{
    const float* p = (const float*)d_in[0];
    const float* q = (const float*)d_in[1];
    float* out = (float*)d_out;

    dim3 block(NTX, NTY);
    dim3 grid((Won + TW - 1) / TW,   // 8
              (Hon + TH - 1) / TH,   // 63
              Bn);                   // 4
    corr9x9_kernel<<<grid, block>>>(p, q, out);
}

// round 4
// speedup vs baseline: 1.0140x; 1.0140x over previous
#include <cuda_runtime.h>

// Problem constants
#define Bn   4
#define Hq   512
#define Wq   512
#define Cn   128
#define Hon  502
#define Won  502
#define OFFS 2
// Tiling
#define TH   8      // output rows per block
#define TW   64     // output cols per block
#define WT   4      // output cols per thread
#define CCK  8      // channel chunk
#define QW   72     // TW + 8 (halo)
#define QR   10     // q rows per dy-group: TH + 2
#define PPAD 68     // padded p width
#define QPAD 76     // padded q width
#define NTX  16
#define NTY  8
#define NTHR 128

// Packed fp32x2 helpers (sm_103a)
#define FMA2(d, a, b) asm("fma.rn.f32x2 %0, %1, %2, %0;" : "+l"(d) : "l"(a), "l"(b))
#define PACK2(r, lo, hi) asm("mov.b64 %0, {%1, %2};" : "=l"(r) : "f"(lo), "f"(hi))
#define UNPACK2(lo, hi, r) asm("mov.b64 {%0, %1}, %2;" : "=f"(lo), "=f"(hi) : "l"(r))

__global__ __launch_bounds__(NTHR, 3)
void corr9x9_kernel(const float* __restrict__ pg,
                    const float* __restrict__ qg,
                    float* __restrict__ outg)
{
    __shared__ __align__(16) float p_s[TH][CCK][PPAD];
    __shared__ __align__(16) float q_s[QR][CCK][QPAD];

    const int tx  = threadIdx.x;
    const int ty  = threadIdx.y;
    const int tid = ty * NTX + tx;

    const int wo0 = blockIdx.x * TW;
    const int ho0 = blockIdx.y * TH;
    const int b   = blockIdx.z;

    const float* pb = pg + (size_t)b * Hon * Won * Cn;
    const float* qb = qg + (size_t)b * Hq  * Wq  * Cn;

    const int ho = ho0 + ty;

    // ---- precompute staging addresses (constant across chunks/groups) ----
    // p staging: 8 iterations
    const float* p_src[8];
    int p_c4[8], p_w[8], p_row[8];
    #pragma unroll
    for (int it = 0; it < 8; ++it) {
        int flat = tid + it * NTHR;
        int c4   = flat & 1;
        int w    = (flat >> 1) & (TW - 1);
        int row  = flat >> 7;
        int hr   = ho0 + row; if (hr > Hon - 1) hr = Hon - 1;
        int wr   = wo0 + w;   if (wr > Won - 1) wr = Won - 1;
        p_src[it] = pb + ((size_t)hr * Won + wr) * Cn + c4 * 4;
        p_c4[it] = c4; p_w[it] = w; p_row[it] = row;
    }

    for (int g = 0; g < 3; ++g) {
        // packed accumulators: pixel pairs (0,1) and (2,3); [pair][d][dx]
        unsigned long long acc[2][3][9];
        #pragma unroll
        for (int k = 0; k < 2; ++k)
            #pragma unroll
            for (int d = 0; d < 3; ++d)
                #pragma unroll
                for (int dx = 0; dx < 9; ++dx)
                    acc[k][d][dx] = 0ull;

        const int r0 = ho0 + 3 * g + OFFS;

        for (int cc = 0; cc < Cn; cc += CCK) {
            __syncthreads();

            // ---- stage p: batch all 8 LDGs, then STS ----
            {
                float4 pv[8];
                #pragma unroll
                for (int it = 0; it < 8; ++it)
                    pv[it] = *(const float4*)(p_src[it] + cc);
                #pragma unroll
                for (int it = 0; it < 8; ++it) {
                    p_s[p_row[it]][p_c4[it] * 4 + 0][p_w[it]] = pv[it].x;
                    p_s[p_row[it]][p_c4[it] * 4 + 1][p_w[it]] = pv[it].y;
                    p_s[p_row[it]][p_c4[it] * 4 + 2][p_w[it]] = pv[it].z;
                    p_s[p_row[it]][p_c4[it] * 4 + 3][p_w[it]] = pv[it].w;
                }
            }

            // ---- stage q: two batches of 6 ----
            #pragma unroll
            for (int half = 0; half < 2; ++half) {
                float4 qv[6];
                int qc4[6], qw[6], qrr[6];
                bool ok[6];
                #pragma unroll
                for (int j = 0; j < 6; ++j) {
                    int flat = tid + (half * 6 + j) * NTHR;
                    ok[j] = (flat < QR * QW * 2);
                    int f  = ok[j] ? flat : 0;
                    int c4 = f & 1;
                    int t  = f >> 1;
                    int w  = t % QW;
                    int rr = t / QW;
                    int hr = r0 + rr;        if (hr > Hq - 1) hr = Hq - 1;
                    int wr = wo0 + OFFS + w; if (wr > Wq - 1) wr = Wq - 1;
                    qc4[j] = c4; qw[j] = w; qrr[j] = rr;
                    if (ok[j])
                        qv[j] = *(const float4*)(qb + ((size_t)hr * Wq + wr) * Cn + cc + c4 * 4);
                }
                #pragma unroll
                for (int j = 0; j < 6; ++j) {
                    if (ok[j]) {
                        q_s[qrr[j]][qc4[j] * 4 + 0][qw[j]] = qv[j].x;
                        q_s[qrr[j]][qc4[j] * 4 + 1][qw[j]] = qv[j].y;
                        q_s[qrr[j]][qc4[j] * 4 + 2][qw[j]] = qv[j].z;
                        q_s[qrr[j]][qc4[j] * 4 + 3][qw[j]] = qv[j].w;
                    }
                }
            }

            __syncthreads();

            // ---- packed compute ----
            #pragma unroll
            for (int c = 0; c < CCK; ++c) {
                const float4 pv = *(const float4*)&p_s[ty][c][tx * WT];
                unsigned long long pp2[2];
                PACK2(pp2[0], pv.x, pv.y);
                PACK2(pp2[1], pv.z, pv.w);

                #pragma unroll
                for (int d = 0; d < 3; ++d) {
                    const float4 a0 = *(const float4*)&q_s[ty + d][c][tx * WT];
                    const float4 a1 = *(const float4*)&q_s[ty + d][c][tx * WT + 4];
                    const float4 a2 = *(const float4*)&q_s[ty + d][c][tx * WT + 8];
                    float qv[12] = {a0.x, a0.y, a0.z, a0.w,
                                    a1.x, a1.y, a1.z, a1.w,
                                    a2.x, a2.y, a2.z, a2.w};
                    // pairs pr[j] = (qv[j], qv[j+1]) for j = 0..10
                    unsigned long long pr[11];
                    #pragma unroll
                    for (int j = 0; j < 11; ++j)
                        PACK2(pr[j], qv[j], qv[j + 1]);

                    #pragma unroll
                    for (int dx = 0; dx < 9; ++dx) {
                        FMA2(acc[0][d][dx], pp2[0], pr[dx]);       // pixels 0,1
                        FMA2(acc[1][d][dx], pp2[1], pr[dx + 2]);   // pixels 2,3
                    }
                }
            }
        }

        // ---- write outputs for this dy-group ----
        if (ho < Hon) {
            #pragma unroll
            for (int k = 0; k < 2; ++k) {
                int wo_lo = wo0 + tx * WT + 2 * k;
                int wo_hi = wo_lo + 1;
                #pragma unroll
                for (int d = 0; d < 3; ++d) {
                    size_t base_lo = ((((size_t)b * Hon + ho) * Won + wo_lo) * 9 + (3 * g + d)) * 9;
                    size_t base_hi = ((((size_t)b * Hon + ho) * Won + wo_hi) * 9 + (3 * g + d)) * 9;
                    #pragma unroll
                    for (int dx = 0; dx < 9; ++dx) {
                        float lo, hi;
                        UNPACK2(lo, hi, acc[k][d][dx]);
                        if (wo_lo < Won) __stcs(&outg[base_lo + dx], lo);
                        if (wo_hi < Won) __stcs(&outg[base_hi + dx], hi);
                    }
                }
            }
        }
    }
}

extern "C" void kernel_launch(void* const* d_in, const int* in_sizes, int n_in,
                              void* d_out, int out_size)
{
    const float* p = (const float*)d_in[0];
    const float* q = (const float*)d_in[1];
    float* out = (float*)d_out;

    dim3 block(NTX, NTY);
    dim3 grid((Won + TW - 1) / TW,   // 8
              (Hon + TH - 1) / TH,   // 63
              Bn);                   // 4
    corr9x9_kernel<<<grid, block>>>(p, q, out);
}